// round 8
// baseline (speedup 1.0000x reference)
#include <cuda_runtime.h>

// VectorQuantizer: z_e [32,64,32,32] f32, emb [1024,64] f32
// out (f32): z_st [2097152], loss, perplexity, encodings [32768 x 1024]

#define ND 64
#define NK 1024
#define HW 1024
#define NN 32768
#define ZELEMS 2097152
#define EPI_BLOCKS (NN / 256)         // 128

typedef unsigned long long u64;

__device__ u64    g_embdup[ND * NK];  // [d][k] = (e_{k,d}, e_{k,d})
__device__ float  g_e2[NK];
__device__ float  g_a[NN];            // ||x_n||^2 (fp32)
__device__ u64    g_best[NN];         // (dist_bits<<32)|code
__device__ int    g_counts[NK];
__device__ double g_losspart[EPI_BLOCKS];

static __device__ __forceinline__ u64 pk2(float lo, float hi) {
    u64 r;
    asm("mov.b64 %0, {%1, %2};" : "=l"(r) : "f"(lo), "f"(hi));
    return r;
}
static __device__ __forceinline__ void upk2(u64 v, float& lo, float& hi) {
    asm("mov.b64 {%0, %1}, %2;" : "=f"(lo), "=f"(hi) : "l"(v));
}
static __device__ __forceinline__ void fma2(u64& acc, u64 a, u64 b) {
    asm("fma.rn.f32x2 %0, %1, %2, %0;" : "+l"(acc) : "l"(a), "l"(b));
}
static __device__ __forceinline__ u64 umin64(u64 a, u64 b) { return a < b ? a : b; }

// ---------------------------------------------------------------------------
// prep_a: duplicated-transposed emb table + e2 + counts + best init. 256x256
// ---------------------------------------------------------------------------
__global__ void vq_prep_a(const float* __restrict__ emb) {
    const int t = blockIdx.x * 256 + threadIdx.x;       // 0..65535
    const int d = t >> 10, k = t & (NK - 1);
    const float e = emb[k * ND + d];
    g_embdup[t] = pk2(e, e);                            // write-coalesced

    if (t < NK) {
        g_counts[t] = 0;
        const float* er = emb + t * ND;
        double s0 = 0.0, s1 = 0.0, s2 = 0.0, s3 = 0.0;  // 4 chains
#pragma unroll
        for (int i = 0; i < 16; i++) {
            double a = (double)er[4 * i],     b = (double)er[4 * i + 1];
            double c = (double)er[4 * i + 2], dd = (double)er[4 * i + 3];
            s0 += a * a; s1 += b * b; s2 += c * c; s3 += dd * dd;
        }
        g_e2[t] = (float)((s0 + s1) + (s2 + s3));
    }
    if (t < NN) g_best[t] = 0xFFFFFFFFFFFFFFFFULL;
}

// ---------------------------------------------------------------------------
// prep_b: row sumsq ||x_n||^2, 4 fp64 chains. 128x256
// ---------------------------------------------------------------------------
__global__ void vq_prep_b(const float* __restrict__ ze) {
    const int t = blockIdx.x * 256 + threadIdx.x;       // 0..32767
    const int b = t >> 10, hw = t & (HW - 1);
    const float* zp = ze + (size_t)b * ND * HW + hw;
    double s0 = 0.0, s1 = 0.0, s2 = 0.0, s3 = 0.0;
#pragma unroll
    for (int i = 0; i < 16; i++) {
        double a = (double)zp[(size_t)(4 * i) * HW];
        double c = (double)zp[(size_t)(4 * i + 1) * HW];
        double d = (double)zp[(size_t)(4 * i + 2) * HW];
        double e = (double)zp[(size_t)(4 * i + 3) * HW];
        s0 += a * a; s1 += c * c; s2 += d * d; s3 += e * e;
    }
    g_a[t] = (float)((s0 + s1) + (s2 + s3));  // integer-ULP offset vs ref: argmin-invariant
}

// ---------------------------------------------------------------------------
// enc_zero: float4 fill of the whole encodings region (head/tail float2).
// enc base = out+ZELEMS+2 is 8-mod-16 -> 2-float head, then aligned float4.
// 4 independent STG.128 per batch, front-loadable for MLP. grid 2048 x 256
// ---------------------------------------------------------------------------
__global__ void vq_enc_zero(float* __restrict__ enc) {
    const int t = blockIdx.x * 256 + threadIdx.x;       // 0..524287
    if (t == 0) {
        *(float2*)enc = make_float2(0.0f, 0.0f);                      // head
        *(float2*)(enc + 2 + 8388607 * 4) = make_float2(0.0f, 0.0f);  // tail
    }
    float4* p = (float4*)(enc + 2);                     // 8388607 aligned slots
    const float4 z4 = make_float4(0.0f, 0.0f, 0.0f, 0.0f);
#pragma unroll
    for (int b4 = 0; b4 < 4; b4++) {                    // 4 batches x 4 stores
        const int s0 = t + (4 * b4) * 524288;
#pragma unroll
        for (int j = 0; j < 4; j++) {
            const int s = s0 + j * 524288;
            if (s < 8388607) p[s] = z4;
        }
    }
}

// ---------------------------------------------------------------------------
// argmin GEMM (round-4 verbatim): block = 64 rows x 256 codes,
// thread = 8 rows x 8 codes, f32x2 over row pairs. grid (512,4) x 256.
// ---------------------------------------------------------------------------
__global__ __launch_bounds__(256, 2) void vq_argmin(const float* __restrict__ ze) {
    __shared__ float xs[ND * 64];   // [d][row] 16 KB

    const int tid = threadIdx.x;
    const int w   = tid >> 5;       // rowgroup: rows 8w..8w+7
    const int g   = tid & 31;       // codegroup lane
    const int row0 = blockIdx.x * 64;
    const int b    = row0 >> 10;
    const int hw0  = row0 & (HW - 1);

    const float* zbase = ze + (size_t)b * ND * HW + hw0;
#pragma unroll
    for (int i = 0; i < 16; i++) {
        const int idx = tid + i * 256;
        const int d = idx >> 6, r = idx & 63;
        xs[idx] = zbase[(size_t)d * HW + r];
    }
    __syncthreads();

    const int cbase = blockIdx.y * 256 + g;             // thread codes: cbase + 32*c
    const u64* __restrict__ bq = g_embdup + cbase;
    const float* xr = xs + 8 * w;

    u64 acc[4][8];
#pragma unroll
    for (int rp = 0; rp < 4; rp++)
#pragma unroll
        for (int c = 0; c < 8; c++) acc[rp][c] = 0ULL;

#pragma unroll 4
    for (int d = 0; d < ND; d++) {
        u64 av[4], bv[8];
#pragma unroll
        for (int rp = 0; rp < 4; rp++)
            av[rp] = *(const u64*)(xr + 2 * rp);        // broadcast LDS.64
#pragma unroll
        for (int c = 0; c < 8; c++) bv[c] = bq[32 * c]; // coalesced LDG.64
#pragma unroll
        for (int c = 0; c < 8; c++)
#pragma unroll
            for (int rp = 0; rp < 4; rp++) fma2(acc[rp][c], av[rp], bv[c]);
        xr += 64;
        bq += NK;
    }

    u64 bestk[8];
#pragma unroll
    for (int r = 0; r < 8; r++) bestk[r] = 0xFFFFFFFFFFFFFFFFULL;

#pragma unroll
    for (int rp = 0; rp < 4; rp++) {
        const float a0 = g_a[row0 + 8 * w + 2 * rp];
        const float a1 = g_a[row0 + 8 * w + 2 * rp + 1];
#pragma unroll
        for (int c = 0; c < 8; c++) {
            const int code = cbase + 32 * c;
            const float e2 = g_e2[code];
            float d0, d1;
            upk2(acc[rp][c], d0, d1);
            const float dist0 = fmaf(-2.0f, d0, a0 + e2);
            const float dist1 = fmaf(-2.0f, d1, a1 + e2);
            const u64 k0 = ((u64)__float_as_uint(dist0) << 32) | (unsigned)code;
            const u64 k1 = ((u64)__float_as_uint(dist1) << 32) | (unsigned)code;
            bestk[2 * rp]     = umin64(bestk[2 * rp], k0);
            bestk[2 * rp + 1] = umin64(bestk[2 * rp + 1], k1);
        }
    }
#pragma unroll
    for (int off = 16; off > 0; off >>= 1) {
#pragma unroll
        for (int r = 0; r < 8; r++) {
            const u64 o = __shfl_down_sync(0xFFFFFFFFu, bestk[r], off);
            bestk[r] = umin64(bestk[r], o);
        }
    }
    if (g == 0) {
#pragma unroll
        for (int r = 0; r < 8; r++)
            atomicMin(&g_best[row0 + 8 * w + r], bestk[r]);
    }
}

// ---------------------------------------------------------------------------
// epilogue: counts, z_st, loss partials (4 fp64 chains). grid 128 x 256
// ---------------------------------------------------------------------------
__global__ __launch_bounds__(256) void vq_epi(const float* __restrict__ ze,
                                              const float* __restrict__ emb,
                                              float* __restrict__ out) {
    __shared__ double red[256];
    const int tid = threadIdx.x;
    const int n = blockIdx.x * 256 + tid;
    const int b = n >> 10, hw = n & (HW - 1);

    const int idx = (int)(g_best[n] & 0xFFFFFFFFULL);
    atomicAdd(&g_counts[idx], 1);

    const float* zp = ze + (size_t)b * ND * HW + hw;
    const float* eq = emb + (size_t)idx * ND;
    float* op = out + (size_t)b * ND * HW + hw;
    double s0 = 0.0, s1 = 0.0, s2 = 0.0, s3 = 0.0;
#pragma unroll
    for (int i = 0; i < 16; i++) {
#pragma unroll
        for (int j = 0; j < 4; j++) {
            const int d = 4 * i + j;
            const float x = zp[(size_t)d * HW];
            const float q = eq[d];
            const float df = q - x;
            op[(size_t)d * HW] = x + df;        // z + (z_q - z), both fp32 roundings
            const float sq = df * df;
            if (j == 0) s0 += (double)sq;
            else if (j == 1) s1 += (double)sq;
            else if (j == 2) s2 += (double)sq;
            else s3 += (double)sq;
        }
    }
    red[tid] = (s0 + s1) + (s2 + s3);
    __syncthreads();
    for (int st = 128; st > 0; st >>= 1) {
        if (tid < st) red[tid] += red[tid + st];
        __syncthreads();
    }
    if (tid == 0) g_losspart[blockIdx.x] = red[0];
}

// ---------------------------------------------------------------------------
// enc_ones: one store per row. grid 128 x 256
// ---------------------------------------------------------------------------
__global__ void vq_enc_ones(float* __restrict__ enc) {
    const int n = blockIdx.x * 256 + threadIdx.x;
    const int idx = (int)(g_best[n] & 0xFFFFFFFFULL);
    enc[(size_t)n * NK + idx] = 1.0f;
}

// ---------------------------------------------------------------------------
// finalize: loss + perplexity. 1 x 256
// ---------------------------------------------------------------------------
__global__ void vq_fin(float* __restrict__ out) {
    __shared__ double se[256];
    __shared__ double sl[256];
    const int t = threadIdx.x;
    double ent = 0.0;
#pragma unroll
    for (int i = 0; i < 4; i++) {
        const int k = t + 256 * i;
        const float p = (float)g_counts[k] / (float)NN;
        ent += (double)(p * logf(p + 1e-10f));
    }
    se[t] = ent;
    sl[t] = (t < EPI_BLOCKS) ? g_losspart[t] : 0.0;
    __syncthreads();
    for (int st = 128; st > 0; st >>= 1) {
        if (t < st) { se[t] += se[t + st]; sl[t] += sl[t + st]; }
        __syncthreads();
    }
    if (t == 0) {
        const float m = (float)(sl[0] / (double)ZELEMS);  // q_latent == e_latent
        out[ZELEMS]     = m + 0.25f * m;
        out[ZELEMS + 1] = expf(-(float)se[0]);
    }
}

extern "C" void kernel_launch(void* const* d_in, const int* in_sizes, int n_in,
                              void* d_out, int out_size) {
    const float* ze  = (const float*)d_in[0];
    const float* emb = (const float*)d_in[1];
    float*       out = (float*)d_out;
    float*       enc = out + (size_t)ZELEMS + 2;

    // launch order chosen so overall launch index 3 == vq_argmin (ncu capture)
    vq_prep_a<<<256, 256>>>(emb);
    vq_prep_b<<<128, 256>>>(ze);
    vq_enc_zero<<<2048, 256>>>(enc);
    vq_argmin<<<dim3(NN / 64, NK / 256), 256>>>(ze);
    vq_epi<<<EPI_BLOCKS, 256>>>(ze, emb, out);
    vq_enc_ones<<<EPI_BLOCKS, 256>>>(enc);
    vq_fin<<<1, 256>>>(out);
}

// round 10
// speedup vs baseline: 1.5335x; 1.5335x over previous
#include <cuda_runtime.h>

// VectorQuantizer: z_e [32,64,32,32] f32, emb [1024,64] f32
// out (f32): z_st [2097152], loss, perplexity, encodings [32768 x 1024]

#define ND 64
#define NK 1024
#define HW 1024
#define NN 32768
#define ZELEMS 2097152
#define EPI_BLOCKS (NN / 256)         // 128
#define ENC4 8388607                  // aligned float4 slots in encodings

typedef unsigned long long u64;

__device__ u64    g_embT[ND * (NK / 2)];  // [d][cp] = (e_{2cp,d}, e_{2cp+1,d}) 256KB
__device__ float  g_e2[NK];
__device__ float  g_a[NN];                // ||x_n||^2 (fp32)
__device__ u64    g_best[NN];             // (dist_bits<<32)|code
__device__ int    g_counts[NK];
__device__ double g_losspart[EPI_BLOCKS];

static __device__ __forceinline__ u64 pk2(float lo, float hi) {
    u64 r;
    asm("mov.b64 %0, {%1, %2};" : "=l"(r) : "f"(lo), "f"(hi));
    return r;
}
static __device__ __forceinline__ void upk2(u64 v, float& lo, float& hi) {
    asm("mov.b64 {%0, %1}, %2;" : "=f"(lo), "=f"(hi) : "l"(v));
}
static __device__ __forceinline__ void fma2(u64& acc, u64 a, u64 b) {
    asm("fma.rn.f32x2 %0, %1, %2, %0;" : "+l"(acc) : "l"(a), "l"(b));
}
static __device__ __forceinline__ u64 umin64(u64 a, u64 b) { return a < b ? a : b; }

// ---------------------------------------------------------------------------
// prep (everything before the GEMM, one kernel): encodings zero-fill,
// embT build, e2, counts, ||x||^2, best init.  grid 2048 x 256
// ---------------------------------------------------------------------------
__global__ void vq_prep(const float* __restrict__ ze,
                        const float* __restrict__ emb,
                        float* __restrict__ enc) {
    const int t = blockIdx.x * 256 + threadIdx.x;       // 0..524287

    if (t == 0) {
        *(float2*)enc = make_float2(0.0f, 0.0f);                   // head
        *(float2*)(enc + 2 + ENC4 * 4) = make_float2(0.0f, 0.0f);  // tail
    }
    // zero-fill: 16 float4 per thread
    {
        float4* p = (float4*)(enc + 2);
        const float4 z4 = make_float4(0.0f, 0.0f, 0.0f, 0.0f);
#pragma unroll
        for (int j = 0; j < 16; j++) {
            const int s = t + j * 524288;
            if (s < ENC4) p[s] = z4;
        }
    }

    if (t < ND * (NK / 2)) {            // embT + best init + ||x||^2
        const int d = t >> 9, cp = t & 511;
        g_embT[t] = pk2(emb[(2 * cp) * ND + d], emb[(2 * cp + 1) * ND + d]);
        g_best[t] = 0xFFFFFFFFFFFFFFFFULL;

        const int b = t >> 10, hw = t & (HW - 1);
        const float* zp = ze + (size_t)b * ND * HW + hw;
        double s0 = 0.0, s1 = 0.0, s2 = 0.0, s3 = 0.0;
#pragma unroll
        for (int i = 0; i < 16; i++) {
            double a = (double)zp[(size_t)(4 * i) * HW];
            double c = (double)zp[(size_t)(4 * i + 1) * HW];
            double dd = (double)zp[(size_t)(4 * i + 2) * HW];
            double e = (double)zp[(size_t)(4 * i + 3) * HW];
            s0 += a * a; s1 += c * c; s2 += dd * dd; s3 += e * e;
        }
        g_a[t] = (float)((s0 + s1) + (s2 + s3));  // integer-ULP offset vs ref: argmin-invariant
    }
    if (t < NK) {
        g_counts[t] = 0;
        const float* er = emb + t * ND;
        double s0 = 0.0, s1 = 0.0, s2 = 0.0, s3 = 0.0;
#pragma unroll
        for (int i = 0; i < 16; i++) {
            double a = (double)er[4 * i],     b = (double)er[4 * i + 1];
            double c = (double)er[4 * i + 2], dd = (double)er[4 * i + 3];
            s0 += a * a; s1 += b * b; s2 += c * c; s3 += dd * dd;
        }
        g_e2[t] = (float)((s0 + s1) + (s2 + s3));
    }
}

// ---------------------------------------------------------------------------
// argmin GEMM, codepair-packed: block = 64 rows x 256 codes (128 codepairs),
// thread = 8 rows x 4 codepairs. x duplicated (x,x) in smem, LDS.128 loads
// two d's; b natural codepairs from embT (half the L1 bytes of round 4).
// Each dot accumulates sequentially over d (identical rounding to round 4).
// grid (512, 4) x 256.
// ---------------------------------------------------------------------------
__global__ __launch_bounds__(256, 2) void vq_argmin(const float* __restrict__ ze) {
    __shared__ u64 xs[64 * ND];     // [row][d] = (x,x), 32 KB

    const int tid = threadIdx.x;
    const int w   = tid >> 5;       // rowgroup: rows 8w..8w+7
    const int g   = tid & 31;       // codepair lane
    const int row0 = blockIdx.x * 64;
    const int b    = row0 >> 10;
    const int hw0  = row0 & (HW - 1);

    // stage x tile duplicated: xs[r][d] = (x,x); global reads coalesced over r
    const float* zbase = ze + (size_t)b * ND * HW + hw0;
#pragma unroll
    for (int i = 0; i < 16; i++) {
        const int idx = tid + i * 256;
        const int d = idx >> 6, r = idx & 63;
        const float x = zbase[(size_t)d * HW + r];
        xs[r * ND + d] = pk2(x, x);
    }
    __syncthreads();

    const int cp0 = blockIdx.y * 128 + g;       // thread codepairs: cp0 + 32*c
    const u64* __restrict__ bq = g_embT + cp0;
    const u64* xr = xs + (8 * w) * ND;

    u64 acc[8][4];
#pragma unroll
    for (int r = 0; r < 8; r++)
#pragma unroll
        for (int c = 0; c < 4; c++) acc[r][c] = 0ULL;

#pragma unroll 4
    for (int d2 = 0; d2 < ND / 2; d2++) {
        u64 b0[4], b1[4];
#pragma unroll
        for (int c = 0; c < 4; c++) {           // coalesced LDG.64 x8 per 2d
            b0[c] = bq[(size_t)(2 * d2) * 512 + 32 * c];
            b1[c] = bq[(size_t)(2 * d2 + 1) * 512 + 32 * c];
        }
#pragma unroll
        for (int r = 0; r < 8; r++) {
            const ulonglong2 av = *(const ulonglong2*)(xr + r * ND + 2 * d2);  // LDS.128 bcast
#pragma unroll
            for (int c = 0; c < 4; c++) fma2(acc[r][c], av.x, b0[c]);
#pragma unroll
            for (int c = 0; c < 4; c++) fma2(acc[r][c], av.y, b1[c]);
        }
    }

    float a[8];
#pragma unroll
    for (int r = 0; r < 8; r++) a[r] = g_a[row0 + 8 * w + r];

    u64 bestk[8];
#pragma unroll
    for (int r = 0; r < 8; r++) bestk[r] = 0xFFFFFFFFFFFFFFFFULL;

#pragma unroll
    for (int c = 0; c < 4; c++) {
        const int code0 = 2 * (cp0 + 32 * c);
        const float2 e2p = *(const float2*)(g_e2 + code0);
#pragma unroll
        for (int r = 0; r < 8; r++) {
            float dot0, dot1;
            upk2(acc[r][c], dot0, dot1);
            const float dist0 = fmaf(-2.0f, dot0, a[r] + e2p.x);  // ref combine order
            const float dist1 = fmaf(-2.0f, dot1, a[r] + e2p.y);
            const u64 k0 = ((u64)__float_as_uint(dist0) << 32) | (unsigned)code0;
            const u64 k1 = ((u64)__float_as_uint(dist1) << 32) | (unsigned)(code0 + 1);
            bestk[r] = umin64(bestk[r], umin64(k0, k1));          // ties -> lowest code
        }
    }
#pragma unroll
    for (int off = 16; off > 0; off >>= 1) {
#pragma unroll
        for (int r = 0; r < 8; r++) {
            const u64 o = __shfl_down_sync(0xFFFFFFFFu, bestk[r], off);
            bestk[r] = umin64(bestk[r], o);
        }
    }
    if (g == 0) {
#pragma unroll
        for (int r = 0; r < 8; r++)
            atomicMin(&g_best[row0 + 8 * w + r], bestk[r]);
    }
}

// ---------------------------------------------------------------------------
// epilogue: counts, one-hot ones, z_st, loss partials. grid 128 x 256
// ---------------------------------------------------------------------------
__global__ __launch_bounds__(256) void vq_epi(const float* __restrict__ ze,
                                              const float* __restrict__ emb,
                                              float* __restrict__ out,
                                              float* __restrict__ enc) {
    __shared__ double red[256];
    const int tid = threadIdx.x;
    const int n = blockIdx.x * 256 + tid;
    const int b = n >> 10, hw = n & (HW - 1);

    const int idx = (int)(g_best[n] & 0xFFFFFFFFULL);
    atomicAdd(&g_counts[idx], 1);
    enc[(size_t)n * NK + idx] = 1.0f;           // zero-fill done in vq_prep

    const float* zp = ze + (size_t)b * ND * HW + hw;
    const float* eq = emb + (size_t)idx * ND;
    float* op = out + (size_t)b * ND * HW + hw;
    double s0 = 0.0, s1 = 0.0, s2 = 0.0, s3 = 0.0;
#pragma unroll
    for (int i = 0; i < 16; i++) {
#pragma unroll
        for (int j = 0; j < 4; j++) {
            const int d = 4 * i + j;
            const float x = zp[(size_t)d * HW];
            const float q = eq[d];
            const float df = q - x;
            op[(size_t)d * HW] = x + df;        // z + (z_q - z), both fp32 roundings
            const float sq = df * df;
            if (j == 0) s0 += (double)sq;
            else if (j == 1) s1 += (double)sq;
            else if (j == 2) s2 += (double)sq;
            else s3 += (double)sq;
        }
    }
    red[tid] = (s0 + s1) + (s2 + s3);
    __syncthreads();
    for (int st = 128; st > 0; st >>= 1) {
        if (tid < st) red[tid] += red[tid + st];
        __syncthreads();
    }
    if (tid == 0) g_losspart[blockIdx.x] = red[0];
}

// ---------------------------------------------------------------------------
// finalize: loss + perplexity. 1 x 256
// ---------------------------------------------------------------------------
__global__ void vq_fin(float* __restrict__ out) {
    __shared__ double se[256];
    __shared__ double sl[256];
    const int t = threadIdx.x;
    double ent = 0.0;
#pragma unroll
    for (int i = 0; i < 4; i++) {
        const int k = t + 256 * i;
        const float p = (float)g_counts[k] / (float)NN;
        ent += (double)(p * logf(p + 1e-10f));
    }
    se[t] = ent;
    sl[t] = (t < EPI_BLOCKS) ? g_losspart[t] : 0.0;
    __syncthreads();
    for (int st = 128; st > 0; st >>= 1) {
        if (t < st) { se[t] += se[t + st]; sl[t] += sl[t + st]; }
        __syncthreads();
    }
    if (t == 0) {
        const float m = (float)(sl[0] / (double)ZELEMS);  // q_latent == e_latent
        out[ZELEMS]     = m + 0.25f * m;
        out[ZELEMS + 1] = expf(-(float)se[0]);
    }
}

extern "C" void kernel_launch(void* const* d_in, const int* in_sizes, int n_in,
                              void* d_out, int out_size) {
    const float* ze  = (const float*)d_in[0];
    const float* emb = (const float*)d_in[1];
    float*       out = (float*)d_out;
    float*       enc = out + (size_t)ZELEMS + 2;

    // 4 launches/call: ncu -s 5 lands on call-2's vq_argmin
    vq_prep<<<2048, 256>>>(ze, emb, enc);
    vq_argmin<<<dim3(NN / 64, NK / 256), 256>>>(ze);
    vq_epi<<<EPI_BLOCKS, 256>>>(ze, emb, out, enc);
    vq_fin<<<1, 256>>>(out);
}